// round 14
// baseline (speedup 1.0000x reference)
#include <cuda_runtime.h>
#include <cuda_fp16.h>
#include <cstdint>

// Problem constants
#define Nn 2
#define Ll 2048
#define Ee 1024
#define Hh 16
#define Dd 64
#define NT (Ll / 64)      // 32 key tiles
#define SQH 72            // smem row stride in halves (144 B)

// Static device scratch (allocation-free per harness rules)
__device__ __align__(16) __half   g_qh[(size_t)Nn * Ll * Ee];        // Q * log2e/32
__device__ __align__(16) __half   g_kh[(size_t)Nn * Ll * Ee];        // K fp16
__device__ __align__(16) __half   g_vt[(size_t)Nn * Hh * Dd * Ll];   // V fp16 transposed
__device__ __align__(16) __half   g_attn_half[(size_t)Nn * Ll * Ee]; // attention out fp16
__device__ __align__(16) __half   g_wh[(size_t)Ee * Ee];             // W fp16
__device__ __align__(16) uint32_t g_mask_bits[(size_t)Nn * Ll * (Ll / 32)];

// ---------------------------------------------------------------------------
// helpers
// ---------------------------------------------------------------------------
__device__ __forceinline__ uint32_t smem_u32(const void* p) {
    uint32_t a;
    asm("{ .reg .u64 t; cvta.to.shared.u64 t, %1; cvt.u32.u64 %0, t; }"
        : "=r"(a) : "l"(p));
    return a;
}

__device__ __forceinline__ void ldmx4(uint32_t& r0, uint32_t& r1,
                                      uint32_t& r2, uint32_t& r3, uint32_t addr) {
    asm volatile("ldmatrix.sync.aligned.m8n8.x4.shared.b16 {%0,%1,%2,%3}, [%4];"
                 : "=r"(r0), "=r"(r1), "=r"(r2), "=r"(r3) : "r"(addr));
}

// f32-accum variant (PV, proj)
__device__ __forceinline__ void mma16816(float c[4], uint32_t a0, uint32_t a1,
                                         uint32_t a2, uint32_t a3,
                                         uint32_t b0, uint32_t b1) {
    asm volatile(
        "mma.sync.aligned.m16n8k16.row.col.f32.f16.f16.f32 "
        "{%0,%1,%2,%3},{%4,%5,%6,%7},{%8,%9},{%0,%1,%2,%3};"
        : "+f"(c[0]), "+f"(c[1]), "+f"(c[2]), "+f"(c[3])
        : "r"(a0), "r"(a1), "r"(a2), "r"(a3), "r"(b0), "r"(b1));
}

// f16-accum variant (QK): C/D = 2x f16x2 regs; c0 = row gid, c1 = row gid+8
__device__ __forceinline__ void mma16816h(uint32_t c[2], uint32_t a0, uint32_t a1,
                                          uint32_t a2, uint32_t a3,
                                          uint32_t b0, uint32_t b1) {
    asm volatile(
        "mma.sync.aligned.m16n8k16.row.col.f16.f16.f16.f16 "
        "{%0,%1},{%2,%3,%4,%5},{%6,%7},{%0,%1};"
        : "+r"(c[0]), "+r"(c[1])
        : "r"(a0), "r"(a1), "r"(a2), "r"(a3), "r"(b0), "r"(b1));
}

// 2^x on both halves
__device__ __forceinline__ uint32_t ex2_h2(uint32_t s) {
    uint32_t d;
    asm("ex2.approx.f16x2 %0, %1;" : "=r"(d) : "r"(s));
    return d;
}
// fp16x2 add (FMA-pipe)
__device__ __forceinline__ uint32_t hadd2u(uint32_t a, uint32_t b) {
    uint32_t d;
    asm("add.f16x2 %0, %1, %2;" : "=r"(d) : "r"(a), "r"(b));
    return d;
}
// raw PTX prmt (generic form). Selector nibble bit 3 = MSB-replicate mode is
// guaranteed by the PTX ISA; the __byte_perm intrinsic drops it (R5 failure).
__device__ __forceinline__ uint32_t prmt(uint32_t a, uint32_t b, uint32_t sel) {
    uint32_t d;
    asm("prmt.b32 %0, %1, %2, %3;" : "=r"(d) : "r"(a), "r"(b), "r"(sel));
    return d;
}

#define CPA16(dst, src) \
    asm volatile("cp.async.cg.shared.global [%0], [%1], 16;" :: "r"(dst), "l"(src))
#define CPA_COMMIT() asm volatile("cp.async.commit_group;" ::: "memory")
#define CPA_WAIT0()  asm volatile("cp.async.wait_group 0;" ::: "memory")

__device__ __forceinline__ uint32_t h2u(__half2 h) { return *reinterpret_cast<uint32_t*>(&h); }

// ===========================================================================
// Merged prepass: one launch covers
//   blocks [0, 1024)            : V transpose -> g_vt (needs smem)
//   blocks [1024, 5120)         : mask -> bitmask (8 words/warp)
//   blocks [5120, PREP_GRID)    : Q/K/W fp16 convert (grid-stride)
// ===========================================================================
#define PREP_VT    1024
#define PREP_MASK  4096
#define PREP_CONV  2048
#define PREP_GRID  (PREP_VT + PREP_MASK + PREP_CONV)   // 7168
#define EQ ((size_t)Nn * Ll * Ee)
#define EW ((size_t)Ee * Ee)

__global__ __launch_bounds__(256) void prep_all(
    const float* __restrict__ Q, const float* __restrict__ K,
    const float* __restrict__ W, const float* __restrict__ V,
    const int* __restrict__ M)
{
    __shared__ float sm[64][65];
    const int b = blockIdx.x;
    const int tid = threadIdx.x;

    if (b < PREP_VT) {
        // ---- V transpose: g_vt[n][h][d][l] ----
        const int l0 = (b & 31) * 64;
        const int yb = b >> 5;
        const int n  = yb >> 4;
        const int h  = yb & 15;
        const float* vb = V + ((size_t)(n * Ll + l0)) * Ee + h * Dd;
        for (int idx = tid; idx < 64 * 16; idx += 256) {
            int r = idx >> 4, c4 = idx & 15;
            float4 v = *reinterpret_cast<const float4*>(vb + (size_t)r * Ee + c4 * 4);
            sm[r][c4 * 4 + 0] = v.x; sm[r][c4 * 4 + 1] = v.y;
            sm[r][c4 * 4 + 2] = v.z; sm[r][c4 * 4 + 3] = v.w;
        }
        __syncthreads();
        const int d = tid >> 2;
        const int lb = (tid & 3) * 16;
        __half* ob = g_vt + (((size_t)(n * Hh + h) * Dd + d)) * Ll + l0 + lb;
        uint32_t pk[8];
        #pragma unroll
        for (int i = 0; i < 8; i++)
            pk[i] = h2u(__floats2half2_rn(sm[lb + 2 * i][d], sm[lb + 2 * i + 1][d]));
        *reinterpret_cast<uint4*>(ob)     = make_uint4(pk[0], pk[1], pk[2], pk[3]);
        *reinterpret_cast<uint4*>(ob + 8) = make_uint4(pk[4], pk[5], pk[6], pk[7]);
    } else if (b < PREP_VT + PREP_MASK) {
        // ---- mask -> bitmask ----
        const int bb = b - PREP_VT;
        const size_t nwords = (size_t)Nn * Ll * (Ll / 32);
        size_t wbase = (((size_t)bb * 256 + tid) >> 5) * 8;
        int lane = tid & 31;
        if (wbase < nwords) {
            int v[8];
            #pragma unroll
            for (int j = 0; j < 8; j++) v[j] = M[(wbase + j) * 32 + lane];
            uint32_t bw[8];
            #pragma unroll
            for (int j = 0; j < 8; j++) bw[j] = __ballot_sync(0xffffffffu, v[j] != 0);
            if (lane == 0) {
                *reinterpret_cast<uint4*>(&g_mask_bits[wbase]) =
                    make_uint4(bw[0], bw[1], bw[2], bw[3]);
                *reinterpret_cast<uint4*>(&g_mask_bits[wbase + 4]) =
                    make_uint4(bw[4], bw[5], bw[6], bw[7]);
            }
        }
    } else {
        // ---- Q/K/W fp16 convert (grid-stride over float4 items) ----
        const int bb = b - PREP_VT - PREP_MASK;
        const size_t q4 = EQ / 4, k4 = EQ / 4, w4 = EW / 4;
        const size_t tot = q4 + k4 + w4;
        const float QSC = 0.045084437f;   // log2(e)/32
        for (size_t i = (size_t)bb * 256 + tid; i < tot;
             i += (size_t)PREP_CONV * 256) {
            const float* src; __half* dst; float sc; size_t j;
            if (i < q4)            { src = Q; dst = g_qh; sc = QSC; j = i; }
            else if (i < q4 + k4)  { src = K; dst = g_kh; sc = 1.0f; j = i - q4; }
            else                   { src = W; dst = g_wh; sc = 1.0f; j = i - q4 - k4; }
            float4 v = reinterpret_cast<const float4*>(src)[j];
            __half2 h0 = __floats2half2_rn(v.x * sc, v.y * sc);
            __half2 h1 = __floats2half2_rn(v.z * sc, v.w * sc);
            reinterpret_cast<uint2*>(dst)[j] = make_uint2(h2u(h0), h2u(h1));
        }
    }
}

// ===========================================================================
// Flash attention (R12 exact revert — best measured config).
// M=64 q-rows/CTA -> 1024 CTAs. 128 threads = 4 warps of m16n64. QK
// f16-accum, PV f32-accum, fused per-n16-subtile pipeline, one __syncthreads
// per tile. Mask via raw prmt.b32 MSB-replicate; lsum via HADD2 tree.
// Grid (L/64, N*H) = (32, 32).
// ===========================================================================
#define SMQ_OFF 0
#define SMK_OFF (64 * SQH * 2)               // 9216 (Q: 64 rows)
#define VOFF    (64 * SQH * 2)               // 9216 (V within stage)
#define STAGE   (2 * 64 * SQH * 2)           // K 64 + V 64 rows = 18432
#define SM_ATT_TOTAL (SMK_OFF + 2 * STAGE)   // 46080 B

__global__ __launch_bounds__(128, 4) void attn_hmma(
    const int* __restrict__ dummy)
{
    extern __shared__ __align__(16) char smem[];
    const uint32_t sb = smem_u32(smem);
    const int tid = threadIdx.x;
    const int lane = tid & 31;
    const int wid = tid >> 5;
    const int gid = lane >> 2, tig = lane & 3;
    const int n = blockIdx.y >> 4;
    const int h = blockIdx.y & 15;
    const int q0 = blockIdx.x * 64;
    const int m0w = wid * 16;

    // ---- preload Q (64 rows) + tile 0 (K/V) via cp.async ----
    {
        const __half* qb = g_qh + ((size_t)(n * Ll + q0)) * Ee + h * Dd;
        #pragma unroll
        for (int i = 0; i < 4; i++) {
            int idx = tid + i * 128;                 // 512 chunks
            int r = idx >> 3, c = idx & 7;
            CPA16(sb + SMQ_OFF + r * 144 + c * 16, qb + (size_t)r * Ee + c * 8);
        }
        const __half* kb = g_kh + ((size_t)(n * Ll)) * Ee + h * Dd;
        const __half* vb = g_vt + ((size_t)(n * Hh + h) * Dd) * Ll;
        #pragma unroll
        for (int i = 0; i < 4; i++) {
            int idx = tid + i * 128;                 // 512 chunks each
            int r = idx >> 3, c = idx & 7;
            CPA16(sb + SMK_OFF + r * 144 + c * 16, kb + (size_t)r * Ee + c * 8);
            CPA16(sb + SMK_OFF + VOFF + r * 144 + c * 16, vb + (size_t)r * Ll + c * 8);
        }
        CPA_COMMIT();
    }

    float O[8][4];
    #pragma unroll
    for (int t = 0; t < 8; t++)
        #pragma unroll
        for (int j = 0; j < 4; j++) O[t][j] = 0.0f;
    float lsum0 = 0.0f, lsum1 = 0.0f;
    uint32_t qf[4][4];                       // Q fragments, loaded once

    const uint32_t aQrow = sb + SMQ_OFF + (m0w + (lane & 15)) * 144 + ((lane >> 4) << 4);
    const uint32_t bRowSel = (((lane >> 4) & 1) << 3) + (lane & 7);
    const uint32_t bKhi    = ((lane >> 3) & 1) << 4;
    const int sh = 2 * tig;

    const uint32_t* mb0 = g_mask_bits + ((size_t)(n * Ll + q0 + m0w + gid)) * (Ll / 32);
    const uint32_t* mb1 = mb0 + (size_t)8 * (Ll / 32);

    for (int kt = 0; kt < NT; kt++) {
        // tile kt data arrived; barrier also proves everyone finished reading
        // the stage that prefetch(kt+1) will overwrite.
        CPA_WAIT0();
        __syncthreads();

        if (kt == 0) {   // Q resident: hoist fragments into registers
            #pragma unroll
            for (int kc = 0; kc < 4; kc++)
                ldmx4(qf[kc][0], qf[kc][1], qf[kc][2], qf[kc][3], aQrow + kc * 32);
        }

        // prefetch next tile into the other stage (overlaps compute below)
        if (kt + 1 < NT) {
            const __half* kb = g_kh + ((size_t)(n * Ll + (kt + 1) * 64)) * Ee + h * Dd;
            const __half* vb = g_vt + ((size_t)(n * Hh + h) * Dd) * Ll + (kt + 1) * 64;
            uint32_t st = sb + SMK_OFF + ((kt + 1) & 1) * STAGE;
            #pragma unroll
            for (int i = 0; i < 4; i++) {
                int idx = tid + i * 128;
                int r = idx >> 3, c = idx & 7;
                CPA16(st + r * 144 + c * 16, kb + (size_t)r * Ee + c * 8);
                CPA16(st + VOFF + r * 144 + c * 16, vb + (size_t)r * Ll + c * 8);
            }
            CPA_COMMIT();
        }

        const uint32_t kbase = sb + SMK_OFF + (kt & 1) * STAGE;
        const uint32_t vbase = kbase + VOFF;

        // ---- mask: vector loads + byte-MSB precompute for prmt ----
        uint2 mw0 = *reinterpret_cast<const uint2*>(&mb0[kt * 2]);
        uint2 mw1 = *reinterpret_cast<const uint2*>(&mb1[kt * 2]);
        uint32_t w0a = mw0.x >> sh, w0b = mw0.y >> sh;
        uint32_t w1a = mw1.x >> sh, w1b = mw1.y >> sh;
        uint32_t bl0a = (w0a & 0x01010101u) << 7, bh0a = (w0a & 0x02020202u) << 6;
        uint32_t bl0b = (w0b & 0x01010101u) << 7, bh0b = (w0b & 0x02020202u) << 6;
        uint32_t bl1a = (w1a & 0x01010101u) << 7, bh1a = (w1a & 0x02020202u) << 6;
        uint32_t bl1b = (w1b & 0x01010101u) << 7, bh1b = (w1b & 0x02020202u) << 6;

        // ---- fused per-n16-subtile: QK_j (f16 accum) -> mask+exp_j -> PV_j ----
        #pragma unroll
        for (int j = 0; j < 4; j++) {
            // S subtile j (keys 16j..16j+15), fp16 accumulators
            uint32_t s0[2] = {0u, 0u};   // n8#0: [row gid | row gid+8] pairs
            uint32_t s1[2] = {0u, 0u};   // n8#1
            #pragma unroll
            for (int kc = 0; kc < 4; kc++) {
                uint32_t b0, b1, b2, b3;
                ldmx4(b0, b1, b2, b3,
                      kbase + (j * 16 + bRowSel) * 144 + kc * 32 + bKhi);
                mma16816h(s0, qf[kc][0], qf[kc][1], qf[kc][2], qf[kc][3], b0, b1);
                mma16816h(s1, qf[kc][0], qf[kc][1], qf[kc][2], qf[kc][3], b2, b3);
            }

            // AND-masks via prmt MSB-replicate (1 instr per 2 elements)
            const int t0 = 2 * j, t1 = 2 * j + 1;
            const uint32_t sel0 = 0xCC88u + (uint32_t)(t0 & 3) * 0x1111u;
            const uint32_t sel1 = 0xCC88u + (uint32_t)(t1 & 3) * 0x1111u;
            uint32_t m00 = (t0 < 4) ? prmt(bl0a, bh0a, sel0) : prmt(bl0b, bh0b, sel0);
            uint32_t m10 = (t0 < 4) ? prmt(bl1a, bh1a, sel0) : prmt(bl1b, bh1b, sel0);
            uint32_t m01 = (t1 < 4) ? prmt(bl0a, bh0a, sel1) : prmt(bl0b, bh0b, sel1);
            uint32_t m11 = (t1 < 4) ? prmt(bl1a, bh1a, sel1) : prmt(bl1b, bh1b, sel1);

            // P = exp2(S) directly on packed mma output
            uint32_t a0 = ex2_h2(s0[0]) & m00;   // row gid,   k lo pair
            uint32_t a1 = ex2_h2(s0[1]) & m10;   // row gid+8, k lo pair
            uint32_t a2 = ex2_h2(s1[0]) & m01;   // row gid,   k hi pair
            uint32_t a3 = ex2_h2(s1[1]) & m11;   // row gid+8, k hi pair

            // row-sum contribution (fma pipe) + fp32 accumulate
            {
                uint32_t t0u = hadd2u(a0, a2);
                uint32_t t1u = hadd2u(a1, a3);
                float2 f0 = __half22float2(*reinterpret_cast<__half2*>(&t0u));
                float2 f1 = __half22float2(*reinterpret_cast<__half2*>(&t1u));
                lsum0 += f0.x + f0.y;
                lsum1 += f1.x + f1.y;
            }

            // PV: O += P_j x V rows 16j..16j+15 (f32 accum)
            #pragma unroll
            for (int jj = 0; jj < 4; jj++) {
                uint32_t v0, v1, v2, v3;
                ldmx4(v0, v1, v2, v3,
                      vbase + (jj * 16 + bRowSel) * 144 + j * 32 + bKhi);
                mma16816(O[2 * jj],     a0, a1, a2, a3, v0, v1);
                mma16816(O[2 * jj + 1], a0, a1, a2, a3, v2, v3);
            }
        }
    }

    // ---- reduce row sums over the 4 tig lanes, normalize, store fp16 ----
    lsum0 += __shfl_xor_sync(0xffffffffu, lsum0, 1);
    lsum0 += __shfl_xor_sync(0xffffffffu, lsum0, 2);
    lsum1 += __shfl_xor_sync(0xffffffffu, lsum1, 1);
    lsum1 += __shfl_xor_sync(0xffffffffu, lsum1, 2);
    float inv0 = 1.0f / lsum0, inv1 = 1.0f / lsum1;

    __half* ob0 = g_attn_half + ((size_t)(n * Ll + q0 + m0w + gid)) * Ee + h * Dd;
    __half* ob1 = ob0 + (size_t)8 * Ee;
    #pragma unroll
    for (int t = 0; t < 8; t++) {
        *reinterpret_cast<uint32_t*>(ob0 + t * 8 + 2 * tig) =
            h2u(__floats2half2_rn(O[t][0] * inv0, O[t][1] * inv0));
        *reinterpret_cast<uint32_t*>(ob1 + t * 8 + 2 * tig) =
            h2u(__floats2half2_rn(O[t][2] * inv1, O[t][3] * inv1));
    }
}

// ===========================================================================
// Projection: out = X W^T + b. fp16 mma (f32 accum). CTA tile m128 x n64 ->
// grid (16, 32) = 512 CTAs (was 256: 1.73-wave quantization wasted ~40% of
// wave 2). Warp layout 4m x 2n of m32 x n32. Double-buffered K chunks of 64.
// ===========================================================================
#define PJ_XB   (128 * SQH * 2)              // X stage bytes: 18432
#define PJ_STAGE (PJ_XB + 64 * SQH * 2)      // + W 64 rows = 27648
#define PJ_TOTAL (2 * PJ_STAGE)              // 55296

__global__ __launch_bounds__(256) void proj_hmma(
    const float* __restrict__ bias, float* __restrict__ out)
{
    extern __shared__ __align__(16) char smem[];
    const uint32_t sb = smem_u32(smem);
    const int tid = threadIdx.x;
    const int lane = tid & 31;
    const int wid = tid >> 5;
    const int gid = lane >> 2, tig = lane & 3;
    const int n0 = blockIdx.x * 64;
    const int m0 = blockIdx.y * 128;
    const int mw = wid & 3, nw = wid >> 2;
    const int m0w = mw * 32;
    const int n0w = nw * 32;

    const uint32_t bRowSel = (((lane >> 4) & 1) << 3) + (lane & 7);
    const uint32_t bKhi    = ((lane >> 3) & 1) << 4;

    auto issue = [&](int kc) {
        const __half* xb = g_attn_half + (size_t)m0 * Ee + kc * 64;
        const __half* wb = g_wh + (size_t)n0 * Ee + kc * 64;
        uint32_t st = sb + (kc & 1) * PJ_STAGE;
        #pragma unroll
        for (int i = 0; i < 4; i++) {          // X: 128 rows x 8 chunks
            int idx = tid + i * 256;
            int r = idx >> 3, c = idx & 7;
            CPA16(st + r * 144 + c * 16, xb + (size_t)r * Ee + c * 8);
        }
        #pragma unroll
        for (int i = 0; i < 2; i++) {          // W: 64 rows x 8 chunks
            int idx = tid + i * 256;
            int r = idx >> 3, c = idx & 7;
            CPA16(st + PJ_XB + r * 144 + c * 16, wb + (size_t)r * Ee + c * 8);
        }
        CPA_COMMIT();
    };

    float C[2][4][4];   // [m16-half][n8-tile][frag]
    #pragma unroll
    for (int hh = 0; hh < 2; hh++)
        #pragma unroll
        for (int t = 0; t < 4; t++)
            #pragma unroll
            for (int j = 0; j < 4; j++) C[hh][t][j] = 0.0f;

    issue(0);

    for (int kc = 0; kc < Ee / 64; kc++) {
        CPA_WAIT0();
        __syncthreads();
        if (kc + 1 < Ee / 64) issue(kc + 1);

        const uint32_t xbase = sb + (kc & 1) * PJ_STAGE;
        const uint32_t wbase = xbase + PJ_XB;

        #pragma unroll
        for (int k4 = 0; k4 < 4; k4++) {
            uint32_t a[2][4];
            #pragma unroll
            for (int hh = 0; hh < 2; hh++)
                ldmx4(a[hh][0], a[hh][1], a[hh][2], a[hh][3],
                      xbase + (m0w + hh * 16 + (lane & 15)) * 144 +
                      ((lane >> 4) << 4) + k4 * 32);
            #pragma unroll
            for (int j = 0; j < 2; j++) {      // n32 = 2 x n16 ldmx4
                uint32_t b0, b1, b2, b3;
                ldmx4(b0, b1, b2, b3,
                      wbase + (n0w + j * 16 + bRowSel) * 144 + k4 * 32 + bKhi);
                #pragma unroll
                for (int hh = 0; hh < 2; hh++) {
                    mma16816(C[hh][2 * j],     a[hh][0], a[hh][1], a[hh][2], a[hh][3], b0, b1);
                    mma16816(C[hh][2 * j + 1], a[hh][0], a[hh][1], a[hh][2], a[hh][3], b2, b3);
                }
            }
        }
    }

    #pragma unroll
    for (int hh = 0; hh < 2; hh++) {
        float* ob0 = out + (size_t)(m0 + m0w + hh * 16 + gid) * Ee + n0 + n0w;
        float* ob1 = ob0 + (size_t)8 * Ee;
        #pragma unroll
        for (int t = 0; t < 4; t++) {
            float2 bv = *reinterpret_cast<const float2*>(bias + n0 + n0w + t * 8 + 2 * tig);
            *reinterpret_cast<float2*>(ob0 + t * 8 + 2 * tig) =
                make_float2(C[hh][t][0] + bv.x, C[hh][t][1] + bv.y);
            *reinterpret_cast<float2*>(ob1 + t * 8 + 2 * tig) =
                make_float2(C[hh][t][2] + bv.x, C[hh][t][3] + bv.y);
        }
    }
}

// ===========================================================================
extern "C" void kernel_launch(void* const* d_in, const int* in_sizes, int n_in,
                              void* d_out, int out_size)
{
    const float* Q = (const float*)d_in[0];
    const float* K = (const float*)d_in[1];
    const float* V = (const float*)d_in[2];
    const int*   M = (const int*)d_in[3];
    const float* W = (const float*)d_in[4];
    const float* b = (const float*)d_in[5];
    float* out = (float*)d_out;

    // merged prepass: V transpose + mask bitpack + Q/K/W convert, one launch
    prep_all<<<PREP_GRID, 256>>>(Q, K, W, V, M);

    // attention (M=64 per CTA -> 1024 CTAs)
    cudaFuncSetAttribute(attn_hmma,
                         cudaFuncAttributeMaxDynamicSharedMemorySize, SM_ATT_TOTAL);
    {
        dim3 g(Ll / 64, Nn * Hh);
        attn_hmma<<<g, 128, SM_ATT_TOTAL>>>(M);
    }

    // projection (m128 x n64 tiles -> 512 CTAs)
    cudaFuncSetAttribute(proj_hmma,
                         cudaFuncAttributeMaxDynamicSharedMemorySize, PJ_TOTAL);
    {
        dim3 g(Ee / 64, (Nn * Ll) / 128);
        proj_hmma<<<g, 256, PJ_TOTAL>>>(b, out);
    }
}

// round 15
// speedup vs baseline: 1.0270x; 1.0270x over previous
#include <cuda_runtime.h>
#include <cuda_fp16.h>
#include <cstdint>

// Problem constants
#define Nn 2
#define Ll 2048
#define Ee 1024
#define Hh 16
#define Dd 64
#define NT (Ll / 64)      // 32 key tiles
#define SQH 72            // smem row stride in halves (144 B)

// Static device scratch (allocation-free per harness rules)
__device__ __align__(16) __half   g_qh[(size_t)Nn * Ll * Ee];        // Q * log2e/32
__device__ __align__(16) __half   g_kh[(size_t)Nn * Ll * Ee];        // K fp16
__device__ __align__(16) __half   g_vt[(size_t)Nn * Hh * Dd * Ll];   // V fp16 transposed
__device__ __align__(16) __half   g_attn_half[(size_t)Nn * Ll * Ee]; // attention out fp16
__device__ __align__(16) __half   g_wh[(size_t)Ee * Ee];             // W fp16
__device__ __align__(16) uint32_t g_mask_bits[(size_t)Nn * Ll * (Ll / 32)];

// ---------------------------------------------------------------------------
// helpers
// ---------------------------------------------------------------------------
__device__ __forceinline__ uint32_t smem_u32(const void* p) {
    uint32_t a;
    asm("{ .reg .u64 t; cvta.to.shared.u64 t, %1; cvt.u32.u64 %0, t; }"
        : "=r"(a) : "l"(p));
    return a;
}

__device__ __forceinline__ void ldmx4(uint32_t& r0, uint32_t& r1,
                                      uint32_t& r2, uint32_t& r3, uint32_t addr) {
    asm volatile("ldmatrix.sync.aligned.m8n8.x4.shared.b16 {%0,%1,%2,%3}, [%4];"
                 : "=r"(r0), "=r"(r1), "=r"(r2), "=r"(r3) : "r"(addr));
}

// f32-accum variant (PV, proj)
__device__ __forceinline__ void mma16816(float c[4], uint32_t a0, uint32_t a1,
                                         uint32_t a2, uint32_t a3,
                                         uint32_t b0, uint32_t b1) {
    asm volatile(
        "mma.sync.aligned.m16n8k16.row.col.f32.f16.f16.f32 "
        "{%0,%1,%2,%3},{%4,%5,%6,%7},{%8,%9},{%0,%1,%2,%3};"
        : "+f"(c[0]), "+f"(c[1]), "+f"(c[2]), "+f"(c[3])
        : "r"(a0), "r"(a1), "r"(a2), "r"(a3), "r"(b0), "r"(b1));
}

// f16-accum variant (QK): C/D = 2x f16x2 regs; c0 = row gid, c1 = row gid+8
__device__ __forceinline__ void mma16816h(uint32_t c[2], uint32_t a0, uint32_t a1,
                                          uint32_t a2, uint32_t a3,
                                          uint32_t b0, uint32_t b1) {
    asm volatile(
        "mma.sync.aligned.m16n8k16.row.col.f16.f16.f16.f16 "
        "{%0,%1},{%2,%3,%4,%5},{%6,%7},{%0,%1};"
        : "+r"(c[0]), "+r"(c[1])
        : "r"(a0), "r"(a1), "r"(a2), "r"(a3), "r"(b0), "r"(b1));
}

// 2^x on both halves
__device__ __forceinline__ uint32_t ex2_h2(uint32_t s) {
    uint32_t d;
    asm("ex2.approx.f16x2 %0, %1;" : "=r"(d) : "r"(s));
    return d;
}
// fp16x2 add (FMA-pipe)
__device__ __forceinline__ uint32_t hadd2u(uint32_t a, uint32_t b) {
    uint32_t d;
    asm("add.f16x2 %0, %1, %2;" : "=r"(d) : "r"(a), "r"(b));
    return d;
}
// raw PTX prmt (generic form). Selector nibble bit 3 = MSB-replicate mode is
// guaranteed by the PTX ISA; the __byte_perm intrinsic drops it (R5 failure).
__device__ __forceinline__ uint32_t prmt(uint32_t a, uint32_t b, uint32_t sel) {
    uint32_t d;
    asm("prmt.b32 %0, %1, %2, %3;" : "=r"(d) : "r"(a), "r"(b), "r"(sel));
    return d;
}

#define CPA16(dst, src) \
    asm volatile("cp.async.cg.shared.global [%0], [%1], 16;" :: "r"(dst), "l"(src))
#define CPA_COMMIT() asm volatile("cp.async.commit_group;" ::: "memory")
#define CPA_WAIT0()  asm volatile("cp.async.wait_group 0;" ::: "memory")

__device__ __forceinline__ uint32_t h2u(__half2 h) { return *reinterpret_cast<uint32_t*>(&h); }

// ===========================================================================
// Merged prepass, longest-job-first block order:
//   blocks [0, PREP_CONV)       : Q/K/W fp16 convert (grid-stride, LONG -> first)
//   blocks [PREP_CONV, +VT)     : V transpose -> g_vt
//   blocks [.., PREP_GRID)      : mask -> bitmask (8 words/warp)
// ===========================================================================
#define PREP_CONV  2048
#define PREP_VT    1024
#define PREP_MASK  4096
#define PREP_GRID  (PREP_CONV + PREP_VT + PREP_MASK)   // 7168
#define EQ ((size_t)Nn * Ll * Ee)
#define EW ((size_t)Ee * Ee)

__global__ __launch_bounds__(256) void prep_all(
    const float* __restrict__ Q, const float* __restrict__ K,
    const float* __restrict__ W, const float* __restrict__ V,
    const int* __restrict__ M)
{
    __shared__ float sm[64][65];
    const int b = blockIdx.x;
    const int tid = threadIdx.x;

    if (b < PREP_CONV) {
        // ---- Q/K/W fp16 convert (grid-stride over float4 items) ----
        const size_t q4 = EQ / 4, k4 = EQ / 4, w4 = EW / 4;
        const size_t tot = q4 + k4 + w4;
        const float QSC = 0.045084437f;   // log2(e)/32
        for (size_t i = (size_t)b * 256 + tid; i < tot;
             i += (size_t)PREP_CONV * 256) {
            const float* src; __half* dst; float sc; size_t j;
            if (i < q4)            { src = Q; dst = g_qh; sc = QSC; j = i; }
            else if (i < q4 + k4)  { src = K; dst = g_kh; sc = 1.0f; j = i - q4; }
            else                   { src = W; dst = g_wh; sc = 1.0f; j = i - q4 - k4; }
            float4 v = reinterpret_cast<const float4*>(src)[j];
            __half2 h0 = __floats2half2_rn(v.x * sc, v.y * sc);
            __half2 h1 = __floats2half2_rn(v.z * sc, v.w * sc);
            reinterpret_cast<uint2*>(dst)[j] = make_uint2(h2u(h0), h2u(h1));
        }
    } else if (b < PREP_CONV + PREP_VT) {
        // ---- V transpose: g_vt[n][h][d][l] ----
        const int bb = b - PREP_CONV;
        const int l0 = (bb & 31) * 64;
        const int yb = bb >> 5;
        const int n  = yb >> 4;
        const int h  = yb & 15;
        const float* vb = V + ((size_t)(n * Ll + l0)) * Ee + h * Dd;
        for (int idx = tid; idx < 64 * 16; idx += 256) {
            int r = idx >> 4, c4 = idx & 15;
            float4 v = *reinterpret_cast<const float4*>(vb + (size_t)r * Ee + c4 * 4);
            sm[r][c4 * 4 + 0] = v.x; sm[r][c4 * 4 + 1] = v.y;
            sm[r][c4 * 4 + 2] = v.z; sm[r][c4 * 4 + 3] = v.w;
        }
        __syncthreads();
        const int d = tid >> 2;
        const int lb = (tid & 3) * 16;
        __half* ob = g_vt + (((size_t)(n * Hh + h) * Dd + d)) * Ll + l0 + lb;
        uint32_t pk[8];
        #pragma unroll
        for (int i = 0; i < 8; i++)
            pk[i] = h2u(__floats2half2_rn(sm[lb + 2 * i][d], sm[lb + 2 * i + 1][d]));
        *reinterpret_cast<uint4*>(ob)     = make_uint4(pk[0], pk[1], pk[2], pk[3]);
        *reinterpret_cast<uint4*>(ob + 8) = make_uint4(pk[4], pk[5], pk[6], pk[7]);
    } else {
        // ---- mask -> bitmask ----
        const int bb = b - PREP_CONV - PREP_VT;
        const size_t nwords = (size_t)Nn * Ll * (Ll / 32);
        size_t wbase = (((size_t)bb * 256 + tid) >> 5) * 8;
        int lane = tid & 31;
        if (wbase < nwords) {
            int v[8];
            #pragma unroll
            for (int j = 0; j < 8; j++) v[j] = M[(wbase + j) * 32 + lane];
            uint32_t bw[8];
            #pragma unroll
            for (int j = 0; j < 8; j++) bw[j] = __ballot_sync(0xffffffffu, v[j] != 0);
            if (lane == 0) {
                *reinterpret_cast<uint4*>(&g_mask_bits[wbase]) =
                    make_uint4(bw[0], bw[1], bw[2], bw[3]);
                *reinterpret_cast<uint4*>(&g_mask_bits[wbase + 4]) =
                    make_uint4(bw[4], bw[5], bw[6], bw[7]);
            }
        }
    }
}

// ===========================================================================
// Flash attention (R12 exact — best measured config).
// M=64 q-rows/CTA -> 1024 CTAs. 128 threads = 4 warps of m16n64. QK
// f16-accum, PV f32-accum, fused per-n16-subtile pipeline, one __syncthreads
// per tile. Mask via raw prmt.b32 MSB-replicate; lsum via HADD2 tree.
// Grid (L/64, N*H) = (32, 32).
// ===========================================================================
#define SMQ_OFF 0
#define SMK_OFF (64 * SQH * 2)               // 9216 (Q: 64 rows)
#define VOFF    (64 * SQH * 2)               // 9216 (V within stage)
#define STAGE   (2 * 64 * SQH * 2)           // K 64 + V 64 rows = 18432
#define SM_ATT_TOTAL (SMK_OFF + 2 * STAGE)   // 46080 B

__global__ __launch_bounds__(128, 4) void attn_hmma(
    const int* __restrict__ dummy)
{
    extern __shared__ __align__(16) char smem[];
    const uint32_t sb = smem_u32(smem);
    const int tid = threadIdx.x;
    const int lane = tid & 31;
    const int wid = tid >> 5;
    const int gid = lane >> 2, tig = lane & 3;
    const int n = blockIdx.y >> 4;
    const int h = blockIdx.y & 15;
    const int q0 = blockIdx.x * 64;
    const int m0w = wid * 16;

    // ---- preload Q (64 rows) + tile 0 (K/V) via cp.async ----
    {
        const __half* qb = g_qh + ((size_t)(n * Ll + q0)) * Ee + h * Dd;
        #pragma unroll
        for (int i = 0; i < 4; i++) {
            int idx = tid + i * 128;                 // 512 chunks
            int r = idx >> 3, c = idx & 7;
            CPA16(sb + SMQ_OFF + r * 144 + c * 16, qb + (size_t)r * Ee + c * 8);
        }
        const __half* kb = g_kh + ((size_t)(n * Ll)) * Ee + h * Dd;
        const __half* vb = g_vt + ((size_t)(n * Hh + h) * Dd) * Ll;
        #pragma unroll
        for (int i = 0; i < 4; i++) {
            int idx = tid + i * 128;                 // 512 chunks each
            int r = idx >> 3, c = idx & 7;
            CPA16(sb + SMK_OFF + r * 144 + c * 16, kb + (size_t)r * Ee + c * 8);
            CPA16(sb + SMK_OFF + VOFF + r * 144 + c * 16, vb + (size_t)r * Ll + c * 8);
        }
        CPA_COMMIT();
    }

    float O[8][4];
    #pragma unroll
    for (int t = 0; t < 8; t++)
        #pragma unroll
        for (int j = 0; j < 4; j++) O[t][j] = 0.0f;
    float lsum0 = 0.0f, lsum1 = 0.0f;
    uint32_t qf[4][4];                       // Q fragments, loaded once

    const uint32_t aQrow = sb + SMQ_OFF + (m0w + (lane & 15)) * 144 + ((lane >> 4) << 4);
    const uint32_t bRowSel = (((lane >> 4) & 1) << 3) + (lane & 7);
    const uint32_t bKhi    = ((lane >> 3) & 1) << 4;
    const int sh = 2 * tig;

    const uint32_t* mb0 = g_mask_bits + ((size_t)(n * Ll + q0 + m0w + gid)) * (Ll / 32);
    const uint32_t* mb1 = mb0 + (size_t)8 * (Ll / 32);

    for (int kt = 0; kt < NT; kt++) {
        // tile kt data arrived; barrier also proves everyone finished reading
        // the stage that prefetch(kt+1) will overwrite.
        CPA_WAIT0();
        __syncthreads();

        if (kt == 0) {   // Q resident: hoist fragments into registers
            #pragma unroll
            for (int kc = 0; kc < 4; kc++)
                ldmx4(qf[kc][0], qf[kc][1], qf[kc][2], qf[kc][3], aQrow + kc * 32);
        }

        // prefetch next tile into the other stage (overlaps compute below)
        if (kt + 1 < NT) {
            const __half* kb = g_kh + ((size_t)(n * Ll + (kt + 1) * 64)) * Ee + h * Dd;
            const __half* vb = g_vt + ((size_t)(n * Hh + h) * Dd) * Ll + (kt + 1) * 64;
            uint32_t st = sb + SMK_OFF + ((kt + 1) & 1) * STAGE;
            #pragma unroll
            for (int i = 0; i < 4; i++) {
                int idx = tid + i * 128;
                int r = idx >> 3, c = idx & 7;
                CPA16(st + r * 144 + c * 16, kb + (size_t)r * Ee + c * 8);
                CPA16(st + VOFF + r * 144 + c * 16, vb + (size_t)r * Ll + c * 8);
            }
            CPA_COMMIT();
        }

        const uint32_t kbase = sb + SMK_OFF + (kt & 1) * STAGE;
        const uint32_t vbase = kbase + VOFF;

        // ---- mask: vector loads + byte-MSB precompute for prmt ----
        uint2 mw0 = *reinterpret_cast<const uint2*>(&mb0[kt * 2]);
        uint2 mw1 = *reinterpret_cast<const uint2*>(&mb1[kt * 2]);
        uint32_t w0a = mw0.x >> sh, w0b = mw0.y >> sh;
        uint32_t w1a = mw1.x >> sh, w1b = mw1.y >> sh;
        uint32_t bl0a = (w0a & 0x01010101u) << 7, bh0a = (w0a & 0x02020202u) << 6;
        uint32_t bl0b = (w0b & 0x01010101u) << 7, bh0b = (w0b & 0x02020202u) << 6;
        uint32_t bl1a = (w1a & 0x01010101u) << 7, bh1a = (w1a & 0x02020202u) << 6;
        uint32_t bl1b = (w1b & 0x01010101u) << 7, bh1b = (w1b & 0x02020202u) << 6;

        // ---- fused per-n16-subtile: QK_j (f16 accum) -> mask+exp_j -> PV_j ----
        #pragma unroll
        for (int j = 0; j < 4; j++) {
            // S subtile j (keys 16j..16j+15), fp16 accumulators
            uint32_t s0[2] = {0u, 0u};   // n8#0: [row gid | row gid+8] pairs
            uint32_t s1[2] = {0u, 0u};   // n8#1
            #pragma unroll
            for (int kc = 0; kc < 4; kc++) {
                uint32_t b0, b1, b2, b3;
                ldmx4(b0, b1, b2, b3,
                      kbase + (j * 16 + bRowSel) * 144 + kc * 32 + bKhi);
                mma16816h(s0, qf[kc][0], qf[kc][1], qf[kc][2], qf[kc][3], b0, b1);
                mma16816h(s1, qf[kc][0], qf[kc][1], qf[kc][2], qf[kc][3], b2, b3);
            }

            // AND-masks via prmt MSB-replicate (1 instr per 2 elements)
            const int t0 = 2 * j, t1 = 2 * j + 1;
            const uint32_t sel0 = 0xCC88u + (uint32_t)(t0 & 3) * 0x1111u;
            const uint32_t sel1 = 0xCC88u + (uint32_t)(t1 & 3) * 0x1111u;
            uint32_t m00 = (t0 < 4) ? prmt(bl0a, bh0a, sel0) : prmt(bl0b, bh0b, sel0);
            uint32_t m10 = (t0 < 4) ? prmt(bl1a, bh1a, sel0) : prmt(bl1b, bh1b, sel0);
            uint32_t m01 = (t1 < 4) ? prmt(bl0a, bh0a, sel1) : prmt(bl0b, bh0b, sel1);
            uint32_t m11 = (t1 < 4) ? prmt(bl1a, bh1a, sel1) : prmt(bl1b, bh1b, sel1);

            // P = exp2(S) directly on packed mma output
            uint32_t a0 = ex2_h2(s0[0]) & m00;   // row gid,   k lo pair
            uint32_t a1 = ex2_h2(s0[1]) & m10;   // row gid+8, k lo pair
            uint32_t a2 = ex2_h2(s1[0]) & m01;   // row gid,   k hi pair
            uint32_t a3 = ex2_h2(s1[1]) & m11;   // row gid+8, k hi pair

            // row-sum contribution (fma pipe) + fp32 accumulate
            {
                uint32_t t0u = hadd2u(a0, a2);
                uint32_t t1u = hadd2u(a1, a3);
                float2 f0 = __half22float2(*reinterpret_cast<__half2*>(&t0u));
                float2 f1 = __half22float2(*reinterpret_cast<__half2*>(&t1u));
                lsum0 += f0.x + f0.y;
                lsum1 += f1.x + f1.y;
            }

            // PV: O += P_j x V rows 16j..16j+15 (f32 accum)
            #pragma unroll
            for (int jj = 0; jj < 4; jj++) {
                uint32_t v0, v1, v2, v3;
                ldmx4(v0, v1, v2, v3,
                      vbase + (jj * 16 + bRowSel) * 144 + j * 32 + bKhi);
                mma16816(O[2 * jj],     a0, a1, a2, a3, v0, v1);
                mma16816(O[2 * jj + 1], a0, a1, a2, a3, v2, v3);
            }
        }
    }

    // ---- reduce row sums over the 4 tig lanes, normalize, store fp16 ----
    lsum0 += __shfl_xor_sync(0xffffffffu, lsum0, 1);
    lsum0 += __shfl_xor_sync(0xffffffffu, lsum0, 2);
    lsum1 += __shfl_xor_sync(0xffffffffu, lsum1, 1);
    lsum1 += __shfl_xor_sync(0xffffffffu, lsum1, 2);
    float inv0 = 1.0f / lsum0, inv1 = 1.0f / lsum1;

    __half* ob0 = g_attn_half + ((size_t)(n * Ll + q0 + m0w + gid)) * Ee + h * Dd;
    __half* ob1 = ob0 + (size_t)8 * Ee;
    #pragma unroll
    for (int t = 0; t < 8; t++) {
        *reinterpret_cast<uint32_t*>(ob0 + t * 8 + 2 * tig) =
            h2u(__floats2half2_rn(O[t][0] * inv0, O[t][1] * inv0));
        *reinterpret_cast<uint32_t*>(ob1 + t * 8 + 2 * tig) =
            h2u(__floats2half2_rn(O[t][2] * inv1, O[t][3] * inv1));
    }
}

// ===========================================================================
// Projection (R12 exact revert): out = X W^T + b. fp16 mma (f32 accum),
// CTA 128x128, warp tile m32 x n64, double-buffered K chunks of 64.
// Grid (E/128, M/128) = (8, 32) = 256 CTAs.
// ===========================================================================
#define PJ_STAGE (2 * 128 * SQH * 2)
#define PJ_TOTAL (2 * PJ_STAGE)

__global__ __launch_bounds__(256) void proj_hmma(
    const float* __restrict__ bias, float* __restrict__ out)
{
    extern __shared__ __align__(16) char smem[];
    const uint32_t sb = smem_u32(smem);
    const int tid = threadIdx.x;
    const int lane = tid & 31;
    const int wid = tid >> 5;
    const int gid = lane >> 2, tig = lane & 3;
    const int n0 = blockIdx.x * 128;
    const int m0 = blockIdx.y * 128;
    const int mw = wid & 3, nw = wid >> 2;
    const int m0w = mw * 32;
    const int n0w = nw * 64;

    const uint32_t bRowSel = (((lane >> 4) & 1) << 3) + (lane & 7);
    const uint32_t bKhi    = ((lane >> 3) & 1) << 4;

    auto issue = [&](int kc) {
        const __half* xb = g_attn_half + (size_t)m0 * Ee + kc * 64;
        const __half* wb = g_wh + (size_t)n0 * Ee + kc * 64;
        uint32_t st = sb + (kc & 1) * PJ_STAGE;
        #pragma unroll
        for (int i = 0; i < 4; i++) {
            int idx = tid + i * 256;
            int r = idx >> 3, c = idx & 7;
            CPA16(st + r * 144 + c * 16, xb + (size_t)r * Ee + c * 8);
            CPA16(st + 128 * SQH * 2 + r * 144 + c * 16, wb + (size_t)r * Ee + c * 8);
        }
        CPA_COMMIT();
    };

    float C[2][8][4];   // [m-half][n8-tile][frag]
    #pragma unroll
    for (int hh = 0; hh < 2; hh++)
        #pragma unroll
        for (int t = 0; t < 8; t++)
            #pragma unroll
            for (int j = 0; j < 4; j++) C[hh][t][j] = 0.0f;

    issue(0);

    for (int kc = 0; kc < Ee / 64; kc++) {
        CPA_WAIT0();
        __syncthreads();
        if (kc + 1 < Ee / 64) issue(kc + 1);

        const uint32_t xbase = sb + (kc & 1) * PJ_STAGE;
        const uint32_t wbase = xbase + 128 * SQH * 2;

        #pragma unroll
        for (int k4 = 0; k4 < 4; k4++) {
            uint32_t a[2][4];
            #pragma unroll
            for (int hh = 0; hh < 2; hh++)
                ldmx4(a[hh][0], a[hh][1], a[hh][2], a[hh][3],
                      xbase + (m0w + hh * 16 + (lane & 15)) * 144 +
                      ((lane >> 4) << 4) + k4 * 32);
            #pragma unroll
            for (int j = 0; j < 4; j++) {
                uint32_t b0, b1, b2, b3;
                ldmx4(b0, b1, b2, b3,
                      wbase + (n0w + j * 16 + bRowSel) * 144 + k4 * 32 + bKhi);
                #pragma unroll
                for (int hh = 0; hh < 2; hh++) {
                    mma16816(C[hh][2 * j],     a[hh][0], a[hh][1], a[hh][2], a[hh][3], b0, b1);
                    mma16816(C[hh][2 * j + 1], a[hh][0], a[hh][1], a[hh][2], a[hh][3], b2, b3);
                }
            }
        }
    }

    #pragma unroll
    for (int hh = 0; hh < 2; hh++) {
        float* ob0 = out + (size_t)(m0 + m0w + hh * 16 + gid) * Ee + n0 + n0w;
        float* ob1 = ob0 + (size_t)8 * Ee;
        #pragma unroll
        for (int t = 0; t < 8; t++) {
            float2 bv = *reinterpret_cast<const float2*>(bias + n0 + n0w + t * 8 + 2 * tig);
            *reinterpret_cast<float2*>(ob0 + t * 8 + 2 * tig) =
                make_float2(C[hh][t][0] + bv.x, C[hh][t][1] + bv.y);
            *reinterpret_cast<float2*>(ob1 + t * 8 + 2 * tig) =
                make_float2(C[hh][t][2] + bv.x, C[hh][t][3] + bv.y);
        }
    }
}

// ===========================================================================
extern "C" void kernel_launch(void* const* d_in, const int* in_sizes, int n_in,
                              void* d_out, int out_size)
{
    const float* Q = (const float*)d_in[0];
    const float* K = (const float*)d_in[1];
    const float* V = (const float*)d_in[2];
    const int*   M = (const int*)d_in[3];
    const float* W = (const float*)d_in[4];
    const float* b = (const float*)d_in[5];
    float* out = (float*)d_out;

    // merged prepass (longest-job-first block order)
    prep_all<<<PREP_GRID, 256>>>(Q, K, W, V, M);

    // attention (M=64 per CTA -> 1024 CTAs)
    cudaFuncSetAttribute(attn_hmma,
                         cudaFuncAttributeMaxDynamicSharedMemorySize, SM_ATT_TOTAL);
    {
        dim3 g(Ll / 64, Nn * Hh);
        attn_hmma<<<g, 128, SM_ATT_TOTAL>>>(M);
    }

    // projection (R12 m128 x n128 tiles, 256 CTAs)
    cudaFuncSetAttribute(proj_hmma,
                         cudaFuncAttributeMaxDynamicSharedMemorySize, PJ_TOTAL);
    {
        dim3 g(Ee / 128, (Nn * Ll) / 128);
        proj_hmma<<<g, 256, PJ_TOTAL>>>(b, out);
    }
}

// round 16
// speedup vs baseline: 1.0285x; 1.0015x over previous
#include <cuda_runtime.h>
#include <cuda_fp16.h>
#include <cstdint>

// Problem constants
#define Nn 2
#define Ll 2048
#define Ee 1024
#define Hh 16
#define Dd 64
#define NT (Ll / 64)      // 32 key tiles
#define SQH 72            // smem row stride in halves (144 B)

// Static device scratch (allocation-free per harness rules)
__device__ __align__(16) __half   g_qh[(size_t)Nn * Ll * Ee];        // Q * log2e/32
__device__ __align__(16) __half   g_kh[(size_t)Nn * Ll * Ee];        // K fp16
__device__ __align__(16) __half   g_vt[(size_t)Nn * Hh * Dd * Ll];   // V fp16 transposed
__device__ __align__(16) __half   g_attn_half[(size_t)Nn * Ll * Ee]; // attention out fp16
__device__ __align__(16) __half   g_wh[(size_t)Ee * Ee];             // W fp16
__device__ __align__(16) uint32_t g_mask_bits[(size_t)Nn * Ll * (Ll / 32)];

// ---------------------------------------------------------------------------
// helpers
// ---------------------------------------------------------------------------
__device__ __forceinline__ uint32_t smem_u32(const void* p) {
    uint32_t a;
    asm("{ .reg .u64 t; cvta.to.shared.u64 t, %1; cvt.u32.u64 %0, t; }"
        : "=r"(a) : "l"(p));
    return a;
}

__device__ __forceinline__ void ldmx4(uint32_t& r0, uint32_t& r1,
                                      uint32_t& r2, uint32_t& r3, uint32_t addr) {
    asm volatile("ldmatrix.sync.aligned.m8n8.x4.shared.b16 {%0,%1,%2,%3}, [%4];"
                 : "=r"(r0), "=r"(r1), "=r"(r2), "=r"(r3) : "r"(addr));
}

// f32-accum variant (PV, proj)
__device__ __forceinline__ void mma16816(float c[4], uint32_t a0, uint32_t a1,
                                         uint32_t a2, uint32_t a3,
                                         uint32_t b0, uint32_t b1) {
    asm volatile(
        "mma.sync.aligned.m16n8k16.row.col.f32.f16.f16.f32 "
        "{%0,%1,%2,%3},{%4,%5,%6,%7},{%8,%9},{%0,%1,%2,%3};"
        : "+f"(c[0]), "+f"(c[1]), "+f"(c[2]), "+f"(c[3])
        : "r"(a0), "r"(a1), "r"(a2), "r"(a3), "r"(b0), "r"(b1));
}

// f16-accum variant (QK): C/D = 2x f16x2 regs; c0 = row gid, c1 = row gid+8
__device__ __forceinline__ void mma16816h(uint32_t c[2], uint32_t a0, uint32_t a1,
                                          uint32_t a2, uint32_t a3,
                                          uint32_t b0, uint32_t b1) {
    asm volatile(
        "mma.sync.aligned.m16n8k16.row.col.f16.f16.f16.f16 "
        "{%0,%1},{%2,%3,%4,%5},{%6,%7},{%0,%1};"
        : "+r"(c[0]), "+r"(c[1])
        : "r"(a0), "r"(a1), "r"(a2), "r"(a3), "r"(b0), "r"(b1));
}

// 2^x on both halves
__device__ __forceinline__ uint32_t ex2_h2(uint32_t s) {
    uint32_t d;
    asm("ex2.approx.f16x2 %0, %1;" : "=r"(d) : "r"(s));
    return d;
}
// fp16x2 add (FMA-pipe)
__device__ __forceinline__ uint32_t hadd2u(uint32_t a, uint32_t b) {
    uint32_t d;
    asm("add.f16x2 %0, %1, %2;" : "=r"(d) : "r"(a), "r"(b));
    return d;
}
// raw PTX prmt (generic form). Selector nibble bit 3 = MSB-replicate mode is
// guaranteed by the PTX ISA; the __byte_perm intrinsic drops it (R5 failure).
__device__ __forceinline__ uint32_t prmt(uint32_t a, uint32_t b, uint32_t sel) {
    uint32_t d;
    asm("prmt.b32 %0, %1, %2, %3;" : "=r"(d) : "r"(a), "r"(b), "r"(sel));
    return d;
}

#define CPA16(dst, src) \
    asm volatile("cp.async.cg.shared.global [%0], [%1], 16;" :: "r"(dst), "l"(src))
#define CPA_COMMIT() asm volatile("cp.async.commit_group;" ::: "memory")
#define CPA_WAIT0()  asm volatile("cp.async.wait_group 0;" ::: "memory")

__device__ __forceinline__ uint32_t h2u(__half2 h) { return *reinterpret_cast<uint32_t*>(&h); }

// ===========================================================================
// Merged prepass, longest-job-first block order:
//   blocks [0, PREP_CONV)       : Q/K/W fp16 convert (grid-stride, LONG -> first)
//   blocks [PREP_CONV, +VT)     : V transpose -> g_vt
//   blocks [.., PREP_GRID)      : mask -> bitmask (8 words/warp)
// ===========================================================================
#define PREP_CONV  2048
#define PREP_VT    1024
#define PREP_MASK  4096
#define PREP_GRID  (PREP_CONV + PREP_VT + PREP_MASK)   // 7168
#define EQ ((size_t)Nn * Ll * Ee)
#define EW ((size_t)Ee * Ee)

__global__ __launch_bounds__(256) void prep_all(
    const float* __restrict__ Q, const float* __restrict__ K,
    const float* __restrict__ W, const float* __restrict__ V,
    const int* __restrict__ M)
{
    __shared__ float sm[64][65];
    const int b = blockIdx.x;
    const int tid = threadIdx.x;

    if (b < PREP_CONV) {
        // ---- Q/K/W fp16 convert (grid-stride over float4 items) ----
        const size_t q4 = EQ / 4, k4 = EQ / 4, w4 = EW / 4;
        const size_t tot = q4 + k4 + w4;
        const float QSC = 0.045084437f;   // log2(e)/32
        for (size_t i = (size_t)b * 256 + tid; i < tot;
             i += (size_t)PREP_CONV * 256) {
            const float* src; __half* dst; float sc; size_t j;
            if (i < q4)            { src = Q; dst = g_qh; sc = QSC; j = i; }
            else if (i < q4 + k4)  { src = K; dst = g_kh; sc = 1.0f; j = i - q4; }
            else                   { src = W; dst = g_wh; sc = 1.0f; j = i - q4 - k4; }
            float4 v = reinterpret_cast<const float4*>(src)[j];
            __half2 h0 = __floats2half2_rn(v.x * sc, v.y * sc);
            __half2 h1 = __floats2half2_rn(v.z * sc, v.w * sc);
            reinterpret_cast<uint2*>(dst)[j] = make_uint2(h2u(h0), h2u(h1));
        }
    } else if (b < PREP_CONV + PREP_VT) {
        // ---- V transpose: g_vt[n][h][d][l] ----
        const int bb = b - PREP_CONV;
        const int l0 = (bb & 31) * 64;
        const int yb = bb >> 5;
        const int n  = yb >> 4;
        const int h  = yb & 15;
        const float* vb = V + ((size_t)(n * Ll + l0)) * Ee + h * Dd;
        for (int idx = tid; idx < 64 * 16; idx += 256) {
            int r = idx >> 4, c4 = idx & 15;
            float4 v = *reinterpret_cast<const float4*>(vb + (size_t)r * Ee + c4 * 4);
            sm[r][c4 * 4 + 0] = v.x; sm[r][c4 * 4 + 1] = v.y;
            sm[r][c4 * 4 + 2] = v.z; sm[r][c4 * 4 + 3] = v.w;
        }
        __syncthreads();
        const int d = tid >> 2;
        const int lb = (tid & 3) * 16;
        __half* ob = g_vt + (((size_t)(n * Hh + h) * Dd + d)) * Ll + l0 + lb;
        uint32_t pk[8];
        #pragma unroll
        for (int i = 0; i < 8; i++)
            pk[i] = h2u(__floats2half2_rn(sm[lb + 2 * i][d], sm[lb + 2 * i + 1][d]));
        *reinterpret_cast<uint4*>(ob)     = make_uint4(pk[0], pk[1], pk[2], pk[3]);
        *reinterpret_cast<uint4*>(ob + 8) = make_uint4(pk[4], pk[5], pk[6], pk[7]);
    } else {
        // ---- mask -> bitmask ----
        const int bb = b - PREP_CONV - PREP_VT;
        const size_t nwords = (size_t)Nn * Ll * (Ll / 32);
        size_t wbase = (((size_t)bb * 256 + tid) >> 5) * 8;
        int lane = tid & 31;
        if (wbase < nwords) {
            int v[8];
            #pragma unroll
            for (int j = 0; j < 8; j++) v[j] = M[(wbase + j) * 32 + lane];
            uint32_t bw[8];
            #pragma unroll
            for (int j = 0; j < 8; j++) bw[j] = __ballot_sync(0xffffffffu, v[j] != 0);
            if (lane == 0) {
                *reinterpret_cast<uint4*>(&g_mask_bits[wbase]) =
                    make_uint4(bw[0], bw[1], bw[2], bw[3]);
                *reinterpret_cast<uint4*>(&g_mask_bits[wbase + 4]) =
                    make_uint4(bw[4], bw[5], bw[6], bw[7]);
            }
        }
    }
}

// ===========================================================================
// Flash attention (R12 exact — best measured config).
// M=64 q-rows/CTA -> 1024 CTAs. 128 threads = 4 warps of m16n64. QK
// f16-accum, PV f32-accum, fused per-n16-subtile pipeline, one __syncthreads
// per tile. Mask via raw prmt.b32 MSB-replicate; lsum via HADD2 tree.
// Grid (L/64, N*H) = (32, 32).
// ===========================================================================
#define SMQ_OFF 0
#define SMK_OFF (64 * SQH * 2)               // 9216 (Q: 64 rows)
#define VOFF    (64 * SQH * 2)               // 9216 (V within stage)
#define STAGE   (2 * 64 * SQH * 2)           // K 64 + V 64 rows = 18432
#define SM_ATT_TOTAL (SMK_OFF + 2 * STAGE)   // 46080 B

__global__ __launch_bounds__(128, 4) void attn_hmma(
    const int* __restrict__ dummy)
{
    extern __shared__ __align__(16) char smem[];
    const uint32_t sb = smem_u32(smem);
    const int tid = threadIdx.x;
    const int lane = tid & 31;
    const int wid = tid >> 5;
    const int gid = lane >> 2, tig = lane & 3;
    const int n = blockIdx.y >> 4;
    const int h = blockIdx.y & 15;
    const int q0 = blockIdx.x * 64;
    const int m0w = wid * 16;

    // ---- preload Q (64 rows) + tile 0 (K/V) via cp.async ----
    {
        const __half* qb = g_qh + ((size_t)(n * Ll + q0)) * Ee + h * Dd;
        #pragma unroll
        for (int i = 0; i < 4; i++) {
            int idx = tid + i * 128;                 // 512 chunks
            int r = idx >> 3, c = idx & 7;
            CPA16(sb + SMQ_OFF + r * 144 + c * 16, qb + (size_t)r * Ee + c * 8);
        }
        const __half* kb = g_kh + ((size_t)(n * Ll)) * Ee + h * Dd;
        const __half* vb = g_vt + ((size_t)(n * Hh + h) * Dd) * Ll;
        #pragma unroll
        for (int i = 0; i < 4; i++) {
            int idx = tid + i * 128;                 // 512 chunks each
            int r = idx >> 3, c = idx & 7;
            CPA16(sb + SMK_OFF + r * 144 + c * 16, kb + (size_t)r * Ee + c * 8);
            CPA16(sb + SMK_OFF + VOFF + r * 144 + c * 16, vb + (size_t)r * Ll + c * 8);
        }
        CPA_COMMIT();
    }

    float O[8][4];
    #pragma unroll
    for (int t = 0; t < 8; t++)
        #pragma unroll
        for (int j = 0; j < 4; j++) O[t][j] = 0.0f;
    float lsum0 = 0.0f, lsum1 = 0.0f;
    uint32_t qf[4][4];                       // Q fragments, loaded once

    const uint32_t aQrow = sb + SMQ_OFF + (m0w + (lane & 15)) * 144 + ((lane >> 4) << 4);
    const uint32_t bRowSel = (((lane >> 4) & 1) << 3) + (lane & 7);
    const uint32_t bKhi    = ((lane >> 3) & 1) << 4;
    const int sh = 2 * tig;

    const uint32_t* mb0 = g_mask_bits + ((size_t)(n * Ll + q0 + m0w + gid)) * (Ll / 32);
    const uint32_t* mb1 = mb0 + (size_t)8 * (Ll / 32);

    for (int kt = 0; kt < NT; kt++) {
        // tile kt data arrived; barrier also proves everyone finished reading
        // the stage that prefetch(kt+1) will overwrite.
        CPA_WAIT0();
        __syncthreads();

        if (kt == 0) {   // Q resident: hoist fragments into registers
            #pragma unroll
            for (int kc = 0; kc < 4; kc++)
                ldmx4(qf[kc][0], qf[kc][1], qf[kc][2], qf[kc][3], aQrow + kc * 32);
        }

        // prefetch next tile into the other stage (overlaps compute below)
        if (kt + 1 < NT) {
            const __half* kb = g_kh + ((size_t)(n * Ll + (kt + 1) * 64)) * Ee + h * Dd;
            const __half* vb = g_vt + ((size_t)(n * Hh + h) * Dd) * Ll + (kt + 1) * 64;
            uint32_t st = sb + SMK_OFF + ((kt + 1) & 1) * STAGE;
            #pragma unroll
            for (int i = 0; i < 4; i++) {
                int idx = tid + i * 128;
                int r = idx >> 3, c = idx & 7;
                CPA16(st + r * 144 + c * 16, kb + (size_t)r * Ee + c * 8);
                CPA16(st + VOFF + r * 144 + c * 16, vb + (size_t)r * Ll + c * 8);
            }
            CPA_COMMIT();
        }

        const uint32_t kbase = sb + SMK_OFF + (kt & 1) * STAGE;
        const uint32_t vbase = kbase + VOFF;

        // ---- mask: vector loads + byte-MSB precompute for prmt ----
        uint2 mw0 = *reinterpret_cast<const uint2*>(&mb0[kt * 2]);
        uint2 mw1 = *reinterpret_cast<const uint2*>(&mb1[kt * 2]);
        uint32_t w0a = mw0.x >> sh, w0b = mw0.y >> sh;
        uint32_t w1a = mw1.x >> sh, w1b = mw1.y >> sh;
        uint32_t bl0a = (w0a & 0x01010101u) << 7, bh0a = (w0a & 0x02020202u) << 6;
        uint32_t bl0b = (w0b & 0x01010101u) << 7, bh0b = (w0b & 0x02020202u) << 6;
        uint32_t bl1a = (w1a & 0x01010101u) << 7, bh1a = (w1a & 0x02020202u) << 6;
        uint32_t bl1b = (w1b & 0x01010101u) << 7, bh1b = (w1b & 0x02020202u) << 6;

        // ---- fused per-n16-subtile: QK_j (f16 accum) -> mask+exp_j -> PV_j ----
        #pragma unroll
        for (int j = 0; j < 4; j++) {
            // S subtile j (keys 16j..16j+15), fp16 accumulators
            uint32_t s0[2] = {0u, 0u};   // n8#0: [row gid | row gid+8] pairs
            uint32_t s1[2] = {0u, 0u};   // n8#1
            #pragma unroll
            for (int kc = 0; kc < 4; kc++) {
                uint32_t b0, b1, b2, b3;
                ldmx4(b0, b1, b2, b3,
                      kbase + (j * 16 + bRowSel) * 144 + kc * 32 + bKhi);
                mma16816h(s0, qf[kc][0], qf[kc][1], qf[kc][2], qf[kc][3], b0, b1);
                mma16816h(s1, qf[kc][0], qf[kc][1], qf[kc][2], qf[kc][3], b2, b3);
            }

            // AND-masks via prmt MSB-replicate (1 instr per 2 elements)
            const int t0 = 2 * j, t1 = 2 * j + 1;
            const uint32_t sel0 = 0xCC88u + (uint32_t)(t0 & 3) * 0x1111u;
            const uint32_t sel1 = 0xCC88u + (uint32_t)(t1 & 3) * 0x1111u;
            uint32_t m00 = (t0 < 4) ? prmt(bl0a, bh0a, sel0) : prmt(bl0b, bh0b, sel0);
            uint32_t m10 = (t0 < 4) ? prmt(bl1a, bh1a, sel0) : prmt(bl1b, bh1b, sel0);
            uint32_t m01 = (t1 < 4) ? prmt(bl0a, bh0a, sel1) : prmt(bl0b, bh0b, sel1);
            uint32_t m11 = (t1 < 4) ? prmt(bl1a, bh1a, sel1) : prmt(bl1b, bh1b, sel1);

            // P = exp2(S) directly on packed mma output
            uint32_t a0 = ex2_h2(s0[0]) & m00;   // row gid,   k lo pair
            uint32_t a1 = ex2_h2(s0[1]) & m10;   // row gid+8, k lo pair
            uint32_t a2 = ex2_h2(s1[0]) & m01;   // row gid,   k hi pair
            uint32_t a3 = ex2_h2(s1[1]) & m11;   // row gid+8, k hi pair

            // row-sum contribution (fma pipe) + fp32 accumulate
            {
                uint32_t t0u = hadd2u(a0, a2);
                uint32_t t1u = hadd2u(a1, a3);
                float2 f0 = __half22float2(*reinterpret_cast<__half2*>(&t0u));
                float2 f1 = __half22float2(*reinterpret_cast<__half2*>(&t1u));
                lsum0 += f0.x + f0.y;
                lsum1 += f1.x + f1.y;
            }

            // PV: O += P_j x V rows 16j..16j+15 (f32 accum)
            #pragma unroll
            for (int jj = 0; jj < 4; jj++) {
                uint32_t v0, v1, v2, v3;
                ldmx4(v0, v1, v2, v3,
                      vbase + (jj * 16 + bRowSel) * 144 + j * 32 + bKhi);
                mma16816(O[2 * jj],     a0, a1, a2, a3, v0, v1);
                mma16816(O[2 * jj + 1], a0, a1, a2, a3, v2, v3);
            }
        }
    }

    // ---- reduce row sums over the 4 tig lanes, normalize, store fp16 ----
    lsum0 += __shfl_xor_sync(0xffffffffu, lsum0, 1);
    lsum0 += __shfl_xor_sync(0xffffffffu, lsum0, 2);
    lsum1 += __shfl_xor_sync(0xffffffffu, lsum1, 1);
    lsum1 += __shfl_xor_sync(0xffffffffu, lsum1, 2);
    float inv0 = 1.0f / lsum0, inv1 = 1.0f / lsum1;

    __half* ob0 = g_attn_half + ((size_t)(n * Ll + q0 + m0w + gid)) * Ee + h * Dd;
    __half* ob1 = ob0 + (size_t)8 * Ee;
    #pragma unroll
    for (int t = 0; t < 8; t++) {
        *reinterpret_cast<uint32_t*>(ob0 + t * 8 + 2 * tig) =
            h2u(__floats2half2_rn(O[t][0] * inv0, O[t][1] * inv0));
        *reinterpret_cast<uint32_t*>(ob1 + t * 8 + 2 * tig) =
            h2u(__floats2half2_rn(O[t][2] * inv1, O[t][3] * inv1));
    }
}

// ===========================================================================
// Projection (R12 exact revert): out = X W^T + b. fp16 mma (f32 accum),
// CTA 128x128, warp tile m32 x n64, double-buffered K chunks of 64.
// Grid (E/128, M/128) = (8, 32) = 256 CTAs.
// ===========================================================================
#define PJ_STAGE (2 * 128 * SQH * 2)
#define PJ_TOTAL (2 * PJ_STAGE)

__global__ __launch_bounds__(256) void proj_hmma(
    const float* __restrict__ bias, float* __restrict__ out)
{
    extern __shared__ __align__(16) char smem[];
    const uint32_t sb = smem_u32(smem);
    const int tid = threadIdx.x;
    const int lane = tid & 31;
    const int wid = tid >> 5;
    const int gid = lane >> 2, tig = lane & 3;
    const int n0 = blockIdx.x * 128;
    const int m0 = blockIdx.y * 128;
    const int mw = wid & 3, nw = wid >> 2;
    const int m0w = mw * 32;
    const int n0w = nw * 64;

    const uint32_t bRowSel = (((lane >> 4) & 1) << 3) + (lane & 7);
    const uint32_t bKhi    = ((lane >> 3) & 1) << 4;

    auto issue = [&](int kc) {
        const __half* xb = g_attn_half + (size_t)m0 * Ee + kc * 64;
        const __half* wb = g_wh + (size_t)n0 * Ee + kc * 64;
        uint32_t st = sb + (kc & 1) * PJ_STAGE;
        #pragma unroll
        for (int i = 0; i < 4; i++) {
            int idx = tid + i * 256;
            int r = idx >> 3, c = idx & 7;
            CPA16(st + r * 144 + c * 16, xb + (size_t)r * Ee + c * 8);
            CPA16(st + 128 * SQH * 2 + r * 144 + c * 16, wb + (size_t)r * Ee + c * 8);
        }
        CPA_COMMIT();
    };

    float C[2][8][4];   // [m-half][n8-tile][frag]
    #pragma unroll
    for (int hh = 0; hh < 2; hh++)
        #pragma unroll
        for (int t = 0; t < 8; t++)
            #pragma unroll
            for (int j = 0; j < 4; j++) C[hh][t][j] = 0.0f;

    issue(0);

    for (int kc = 0; kc < Ee / 64; kc++) {
        CPA_WAIT0();
        __syncthreads();
        if (kc + 1 < Ee / 64) issue(kc + 1);

        const uint32_t xbase = sb + (kc & 1) * PJ_STAGE;
        const uint32_t wbase = xbase + 128 * SQH * 2;

        #pragma unroll
        for (int k4 = 0; k4 < 4; k4++) {
            uint32_t a[2][4];
            #pragma unroll
            for (int hh = 0; hh < 2; hh++)
                ldmx4(a[hh][0], a[hh][1], a[hh][2], a[hh][3],
                      xbase + (m0w + hh * 16 + (lane & 15)) * 144 +
                      ((lane >> 4) << 4) + k4 * 32);
            #pragma unroll
            for (int j = 0; j < 4; j++) {
                uint32_t b0, b1, b2, b3;
                ldmx4(b0, b1, b2, b3,
                      wbase + (n0w + j * 16 + bRowSel) * 144 + k4 * 32 + bKhi);
                #pragma unroll
                for (int hh = 0; hh < 2; hh++) {
                    mma16816(C[hh][2 * j],     a[hh][0], a[hh][1], a[hh][2], a[hh][3], b0, b1);
                    mma16816(C[hh][2 * j + 1], a[hh][0], a[hh][1], a[hh][2], a[hh][3], b2, b3);
                }
            }
        }
    }

    #pragma unroll
    for (int hh = 0; hh < 2; hh++) {
        float* ob0 = out + (size_t)(m0 + m0w + hh * 16 + gid) * Ee + n0 + n0w;
        float* ob1 = ob0 + (size_t)8 * Ee;
        #pragma unroll
        for (int t = 0; t < 8; t++) {
            float2 bv = *reinterpret_cast<const float2*>(bias + n0 + n0w + t * 8 + 2 * tig);
            *reinterpret_cast<float2*>(ob0 + t * 8 + 2 * tig) =
                make_float2(C[hh][t][0] + bv.x, C[hh][t][1] + bv.y);
            *reinterpret_cast<float2*>(ob1 + t * 8 + 2 * tig) =
                make_float2(C[hh][t][2] + bv.x, C[hh][t][3] + bv.y);
        }
    }
}

// ===========================================================================
extern "C" void kernel_launch(void* const* d_in, const int* in_sizes, int n_in,
                              void* d_out, int out_size)
{
    const float* Q = (const float*)d_in[0];
    const float* K = (const float*)d_in[1];
    const float* V = (const float*)d_in[2];
    const int*   M = (const int*)d_in[3];
    const float* W = (const float*)d_in[4];
    const float* b = (const float*)d_in[5];
    float* out = (float*)d_out;

    // merged prepass (longest-job-first block order)
    prep_all<<<PREP_GRID, 256>>>(Q, K, W, V, M);

    // attention (M=64 per CTA -> 1024 CTAs)
    cudaFuncSetAttribute(attn_hmma,
                         cudaFuncAttributeMaxDynamicSharedMemorySize, SM_ATT_TOTAL);
    {
        dim3 g(Ll / 64, Nn * Hh);
        attn_hmma<<<g, 128, SM_ATT_TOTAL>>>(M);
    }

    // projection (R12 m128 x n128 tiles, 256 CTAs)
    cudaFuncSetAttribute(proj_hmma,
                         cudaFuncAttributeMaxDynamicSharedMemorySize, PJ_TOTAL);
    {
        dim3 g(Ee / 128, (Nn * Ll) / 128);
        proj_hmma<<<g, 256, PJ_TOTAL>>>(b, out);
    }
}